// round 2
// baseline (speedup 1.0000x reference)
#include <cuda_runtime.h>
#include <cstdint>
#include <cstddef>

// Problem dims (fixed for this dataset)
#define BB 4
#define KSEQ 4096
#define DD 2048
#define M_TOTAL (BB * KSEQ)   // 16384 rows

// Scratch: lam[b,k,e] fp32, 128 MiB. __device__ global per allocation rules.
__device__ float g_lam[(size_t)BB * KSEQ * DD];

// ---------------------------------------------------------------------------
// GEMM + bias + sigmoid:  g_lam[m, e] = sigmoid( sum_d x[m,d] * W[e,d] + b[e] )
// A = x [M, D] row-major; B = W [D_out, D_in] row-major (K-major for both) ->
// C = A * B^T, exactly mma.sync row.col form.
// TF32 m16n8k8, tile BM=128 x BN=64 x BK=32, 256 threads (8 warps, 4x2),
// each warp owns a 32x32 sub-tile = 2(m) x 4(n) MMA fragments.
// ---------------------------------------------------------------------------
#define BM 128
#define BN 64
#define BKT 32
#define GEMM_THREADS 256

__device__ __forceinline__ float sigmoidf_fast(float z) {
    return 1.0f / (1.0f + __expf(-z));
}

__device__ __forceinline__ uint32_t f32_to_tf32(float v) {
    uint32_t r;
    asm("cvt.rna.tf32.f32 %0, %1;" : "=r"(r) : "f"(v));
    return r;
}

__global__ __launch_bounds__(GEMM_THREADS)
void gemm_sigmoid_kernel(const float* __restrict__ A,
                         const float* __restrict__ W,
                         const float* __restrict__ bias) {
    __shared__ uint32_t As[BKT][BM + 4];
    __shared__ uint32_t Bs[BKT][BN + 4];

    const int tid  = threadIdx.x;
    const int m0   = blockIdx.y * BM;
    const int n0   = blockIdx.x * BN;
    const int warp = tid >> 5;
    const int lane = tid & 31;
    const int wm   = (warp >> 1) * 32;   // warp m offset within block tile
    const int wn   = (warp & 1) * 32;    // warp n offset within block tile
    const int g    = lane >> 2;          // group id 0..7
    const int t4   = lane & 3;           // thread-in-group 0..3

    float acc[2][4][4];
#pragma unroll
    for (int i = 0; i < 2; i++)
#pragma unroll
        for (int j = 0; j < 4; j++)
#pragma unroll
            for (int c = 0; c < 4; c++) acc[i][j][c] = 0.0f;

    for (int kk = 0; kk < DD; kk += BKT) {
        // --- load A tile 128x32 (transposed into [k][m] smem) ---
#pragma unroll
        for (int i = 0; i < 4; i++) {
            int f4  = i * GEMM_THREADS + tid;   // 0..1023 float4s
            int row = f4 >> 3;                  // 0..127
            int c4  = f4 & 7;                   // 0..7
            float4 v = *reinterpret_cast<const float4*>(
                &A[(size_t)(m0 + row) * DD + kk + c4 * 4]);
            As[c4 * 4 + 0][row] = f32_to_tf32(v.x);
            As[c4 * 4 + 1][row] = f32_to_tf32(v.y);
            As[c4 * 4 + 2][row] = f32_to_tf32(v.z);
            As[c4 * 4 + 3][row] = f32_to_tf32(v.w);
        }
        // --- load B tile 64x32 (W rows = output channels e) ---
#pragma unroll
        for (int i = 0; i < 2; i++) {
            int f4  = i * GEMM_THREADS + tid;   // 0..511
            int row = f4 >> 3;                  // 0..63
            int c4  = f4 & 7;
            float4 v = *reinterpret_cast<const float4*>(
                &W[(size_t)(n0 + row) * DD + kk + c4 * 4]);
            Bs[c4 * 4 + 0][row] = f32_to_tf32(v.x);
            Bs[c4 * 4 + 1][row] = f32_to_tf32(v.y);
            Bs[c4 * 4 + 2][row] = f32_to_tf32(v.z);
            Bs[c4 * 4 + 3][row] = f32_to_tf32(v.w);
        }
        __syncthreads();

#pragma unroll
        for (int ks = 0; ks < BKT; ks += 8) {
            // A fragments: 2 m-tiles of 16 rows
            uint32_t afr[2][4];
#pragma unroll
            for (int mt = 0; mt < 2; mt++) {
                int r = wm + mt * 16 + g;
                afr[mt][0] = As[ks + t4][r];
                afr[mt][1] = As[ks + t4][r + 8];
                afr[mt][2] = As[ks + t4 + 4][r];
                afr[mt][3] = As[ks + t4 + 4][r + 8];
            }
            // B fragments: 4 n-tiles of 8 cols
            uint32_t bfr[4][2];
#pragma unroll
            for (int nt = 0; nt < 4; nt++) {
                int c = wn + nt * 8 + g;
                bfr[nt][0] = Bs[ks + t4][c];
                bfr[nt][1] = Bs[ks + t4 + 4][c];
            }
#pragma unroll
            for (int mt = 0; mt < 2; mt++) {
#pragma unroll
                for (int nt = 0; nt < 4; nt++) {
                    asm volatile(
                        "mma.sync.aligned.m16n8k8.row.col.f32.tf32.tf32.f32 "
                        "{%0,%1,%2,%3}, {%4,%5,%6,%7}, {%8,%9}, {%0,%1,%2,%3};"
                        : "+f"(acc[mt][nt][0]), "+f"(acc[mt][nt][1]),
                          "+f"(acc[mt][nt][2]), "+f"(acc[mt][nt][3])
                        : "r"(afr[mt][0]), "r"(afr[mt][1]),
                          "r"(afr[mt][2]), "r"(afr[mt][3]),
                          "r"(bfr[nt][0]), "r"(bfr[nt][1]));
                }
            }
        }
        __syncthreads();
    }

    // Epilogue: bias + sigmoid -> g_lam
#pragma unroll
    for (int mt = 0; mt < 2; mt++) {
#pragma unroll
        for (int nt = 0; nt < 4; nt++) {
            int row = m0 + wm + mt * 16 + g;
            int col = n0 + wn + nt * 8 + t4 * 2;
            float b0 = bias[col];
            float b1 = bias[col + 1];
            g_lam[(size_t)row * DD + col]           = sigmoidf_fast(acc[mt][nt][0] + b0);
            g_lam[(size_t)row * DD + col + 1]       = sigmoidf_fast(acc[mt][nt][1] + b1);
            g_lam[(size_t)(row + 8) * DD + col]     = sigmoidf_fast(acc[mt][nt][2] + b0);
            g_lam[(size_t)(row + 8) * DD + col + 1] = sigmoidf_fast(acc[mt][nt][3] + b1);
        }
    }
}

// ---------------------------------------------------------------------------
// Gated linear recurrence: per channel (b,d):
//   s_k = lam_k * s_{k-1} + (1 - lam_k) * x_k  =  fma(lam_k, s_{k-1} - x_k, x_k)
// One thread per channel (8192 threads). Unroll x8 with batched prefetch so
// loads stay independent of the carried dependency chain.
// ---------------------------------------------------------------------------
__global__ __launch_bounds__(128)
void scan_kernel(const float* __restrict__ x, float* __restrict__ out) {
    int ch = blockIdx.x * blockDim.x + threadIdx.x;   // 0..8191
    int b = ch / DD;
    int d = ch % DD;
    const size_t base = (size_t)b * KSEQ * DD + d;

    float s = 0.0f;
    for (int k0 = 0; k0 < KSEQ; k0 += 8) {
        float l[8], u[8];
#pragma unroll
        for (int j = 0; j < 8; j++) {
            size_t idx = base + (size_t)(k0 + j) * DD;
            l[j] = g_lam[idx];
            u[j] = x[idx];
        }
#pragma unroll
        for (int j = 0; j < 8; j++) {
            s = fmaf(l[j], s - u[j], u[j]);
            out[base + (size_t)(k0 + j) * DD] = s;
        }
    }
}

// ---------------------------------------------------------------------------
extern "C" void kernel_launch(void* const* d_in, const int* in_sizes, int n_in,
                              void* d_out, int out_size) {
    const float* x    = (const float*)d_in[0];   // [B,K,D]
    const float* W    = (const float*)d_in[1];   // [D,D]
    const float* bias = (const float*)d_in[2];   // [D]
    float* out = (float*)d_out;                  // [B,K,D]

    dim3 ggrid(DD / BN, M_TOTAL / BM);           // (32, 128)
    gemm_sigmoid_kernel<<<ggrid, GEMM_THREADS>>>(x, W, bias);

    scan_kernel<<<(BB * DD) / 128, 128>>>(x, out);
}

// round 5
// speedup vs baseline: 2.2808x; 2.2808x over previous
#include <cuda_runtime.h>
#include <cstdint>
#include <cstddef>

// Problem dims (fixed)
#define BB 4
#define KSEQ 4096
#define DD 2048
#define M_TOTAL (BB * KSEQ)   // 16384

// Scratch: lam[m,e] fp32 (128 MB). __device__ global per allocation rules.
__device__ float g_lam[(size_t)M_TOTAL * DD];

// ---------------------------------------------------------------------------
// GEMM + bias + sigmoid via legacy mma.sync (tf32 m16n8k8):
//   g_lam[m,e] = sigmoid( sum_d x[m,d] * W[e,d] + b[e] )
// Block 128x128x32, 256 threads (8 warps, 2x4), warp tile 64x32.
// 3-stage cp.async pipeline; smem rows padded to 36 floats for conflict-free
// fragment loads (bank = (4*row + k) % 32, distinct across the warp).
// ---------------------------------------------------------------------------
#define Bb 128            // block M
#define BN 128            // block N
#define BK 32             // block K
#define STAGES 3
#define PAD 36            // floats per smem row
#define A_ST_FLOATS (Bb * PAD)
#define B_ST_FLOATS (BN * PAD)
#define STAGE_FLOATS (A_ST_FLOATS + B_ST_FLOATS)
#define GEMM_SMEM (STAGES * STAGE_FLOATS * 4)     // 110592 B
#define GEMM_THREADS 256

__device__ __forceinline__ uint32_t smem_u32(const void* p) {
    uint32_t a;
    asm("{ .reg .u64 t; cvta.to.shared.u64 t, %1; cvt.u32.u64 %0, t; }" : "=r"(a) : "l"(p));
    return a;
}
__device__ __forceinline__ void cpa16(uint32_t dst, const void* src) {
    asm volatile("cp.async.cg.shared.global [%0], [%1], 16;" :: "r"(dst), "l"(src) : "memory");
}
#define CP_COMMIT() asm volatile("cp.async.commit_group;" ::: "memory")
#define CP_WAIT(n)  asm volatile("cp.async.wait_group %0;" :: "n"(n) : "memory")

__device__ __forceinline__ uint32_t f32_to_tf32(float v) {
    uint32_t r;
    asm("cvt.rna.tf32.f32 %0, %1;" : "=r"(r) : "f"(v));
    return r;
}
__device__ __forceinline__ float sigmoidf_fast(float z) {
    return 1.0f / (1.0f + __expf(-z));
}

__global__ __launch_bounds__(GEMM_THREADS, 2)
void gemm_sigmoid_kernel(const float* __restrict__ A,      // x [M, D]
                         const float* __restrict__ W,      // W [D_out, D_in]
                         const float* __restrict__ bias) {
    extern __shared__ float smem[];
    // stage s: A at smem + s*STAGE_FLOATS, B at +A_ST_FLOATS
    const int tid  = threadIdx.x;
    const int warp = tid >> 5;
    const int lane = tid & 31;
    const int m0   = blockIdx.y * Bb;
    const int n0   = blockIdx.x * BN;
    const int wm   = (warp >> 2) * 64;     // 2 warp-rows
    const int wn   = (warp & 3) * 32;      // 4 warp-cols
    const int g    = lane >> 2;            // 0..7
    const int t4   = lane & 3;             // 0..3

    // cp.async source/dest indexing: each thread moves 4 x 16B per tile
    const int ldr = tid >> 3;              // row 0..31 step -> combined below
    const int lds = tid & 7;               // 16B segment 0..7 (k0 = seg*4)

    const uint32_t smem_base = smem_u32(smem);

    float acc[4][4][4];
#pragma unroll
    for (int i = 0; i < 4; i++)
#pragma unroll
        for (int j = 0; j < 4; j++)
#pragma unroll
            for (int c = 0; c < 4; c++) acc[i][j][c] = 0.0f;

    const int NKT = DD / BK;   // 64 chunks

    // ---- stage loader ----
    auto load_stage = [&](int kt, int s) {
        const int kk = kt * BK;
        const uint32_t sa = smem_base + (uint32_t)(s * STAGE_FLOATS) * 4u;
        const uint32_t sb = sa + (uint32_t)A_ST_FLOATS * 4u;
#pragma unroll
        for (int i = 0; i < 4; i++) {
            int row = i * 32 + ldr;        // 0..127
            cpa16(sa + (uint32_t)(row * PAD + lds * 4) * 4u,
                  A + (size_t)(m0 + row) * DD + kk + lds * 4);
        }
#pragma unroll
        for (int i = 0; i < 4; i++) {
            int row = i * 32 + ldr;
            cpa16(sb + (uint32_t)(row * PAD + lds * 4) * 4u,
                  W + (size_t)(n0 + row) * DD + kk + lds * 4);
        }
        CP_COMMIT();
    };

    // prologue: stages 0..STAGES-2
    load_stage(0, 0);
    load_stage(1, 1);

    for (int kt = 0; kt < NKT; kt++) {
        CP_WAIT(STAGES - 2);
        __syncthreads();

        const int s = kt % STAGES;
        const float* sA = smem + s * STAGE_FLOATS;
        const float* sB = sA + A_ST_FLOATS;

#pragma unroll
        for (int ks = 0; ks < BK; ks += 8) {
            // A fragments: 4 m-tiles (64 rows)
            uint32_t afr[4][4];
#pragma unroll
            for (int mt = 0; mt < 4; mt++) {
                const float* ap = sA + (wm + mt * 16 + g) * PAD + ks + t4;
                afr[mt][0] = f32_to_tf32(ap[0]);
                afr[mt][1] = f32_to_tf32(ap[8 * PAD]);
                afr[mt][2] = f32_to_tf32(ap[4]);
                afr[mt][3] = f32_to_tf32(ap[8 * PAD + 4]);
            }
            // B fragments: 4 n-tiles (32 cols)
            uint32_t bfr[4][2];
#pragma unroll
            for (int nt = 0; nt < 4; nt++) {
                const float* bp = sB + (wn + nt * 8 + g) * PAD + ks + t4;
                bfr[nt][0] = f32_to_tf32(bp[0]);
                bfr[nt][1] = f32_to_tf32(bp[4]);
            }
#pragma unroll
            for (int mt = 0; mt < 4; mt++) {
#pragma unroll
                for (int nt = 0; nt < 4; nt++) {
                    asm volatile(
                        "mma.sync.aligned.m16n8k8.row.col.f32.tf32.tf32.f32 "
                        "{%0,%1,%2,%3}, {%4,%5,%6,%7}, {%8,%9}, {%0,%1,%2,%3};"
                        : "+f"(acc[mt][nt][0]), "+f"(acc[mt][nt][1]),
                          "+f"(acc[mt][nt][2]), "+f"(acc[mt][nt][3])
                        : "r"(afr[mt][0]), "r"(afr[mt][1]),
                          "r"(afr[mt][2]), "r"(afr[mt][3]),
                          "r"(bfr[nt][0]), "r"(bfr[nt][1]));
                }
            }
        }
        __syncthreads();

        if (kt + STAGES - 1 < NKT)
            load_stage(kt + STAGES - 1, (kt + STAGES - 1) % STAGES);
        else
            CP_COMMIT();   // keep group count consistent
    }

    // Epilogue: bias + sigmoid -> g_lam (float2 stores: t4*2 .. t4*2+1)
#pragma unroll
    for (int mt = 0; mt < 4; mt++) {
#pragma unroll
        for (int half = 0; half < 2; half++) {
            const int row = m0 + wm + mt * 16 + g + half * 8;
            float* dst = g_lam + (size_t)row * DD;
#pragma unroll
            for (int nt = 0; nt < 4; nt++) {
                const int col = n0 + wn + nt * 8 + t4 * 2;
                float2 v;
                v.x = sigmoidf_fast(acc[mt][nt][2 * half + 0] + __ldg(bias + col));
                v.y = sigmoidf_fast(acc[mt][nt][2 * half + 1] + __ldg(bias + col + 1));
                *reinterpret_cast<float2*>(dst + col) = v;
            }
        }
    }
}

// ---------------------------------------------------------------------------
// Chunked 2-phase scan. Block: 32 channels (lane) x 32 chunk-warps (1024 thr).
// K=4096 = 32 chunks of 128. Phase A: per-chunk (prod lam, partial scan);
// smem combine for carries; phase B: replay with carry and write out.
// ---------------------------------------------------------------------------
#define SC_CHUNKS 32
#define SC_L (KSEQ / SC_CHUNKS)   // 128
__global__ __launch_bounds__(1024)
void scan_kernel(const float* __restrict__ x, float* __restrict__ out) {
    __shared__ float sP[SC_CHUNKS][33];
    __shared__ float sQ[SC_CHUNKS][33];
    const int lane = threadIdx.x & 31;
    const int ck   = threadIdx.x >> 5;
    const int ch   = blockIdx.x * 32 + lane;
    const int b    = ch >> 11;            // /DD
    const int d    = ch & (DD - 1);
    const size_t base = ((size_t)b * KSEQ + (size_t)ck * SC_L) * DD + d;

    // phase A: chunk summary
    float s = 0.0f, p = 1.0f;
    {
        size_t idx = base;
#pragma unroll 4
        for (int j = 0; j < SC_L; j++) {
            float lm = __ldg(g_lam + idx);
            float u  = __ldg(x + idx);
            s = fmaf(lm, s - u, u);
            p *= lm;
            idx += DD;
        }
    }
    sP[ck][lane] = p;
    sQ[ck][lane] = s;
    __syncthreads();

    // carry entering this chunk
    float carry = 0.0f;
    for (int j = 0; j < ck; j++) carry = fmaf(sP[j][lane], carry, sQ[j][lane]);

    // phase B: replay with carry
    {
        size_t idx = base;
        float ss = carry;
#pragma unroll 4
        for (int j = 0; j < SC_L; j++) {
            float lm = __ldg(g_lam + idx);
            float u  = __ldg(x + idx);
            ss = fmaf(lm, ss - u, u);
            out[idx] = ss;
            idx += DD;
        }
    }
}

// ---------------------------------------------------------------------------
extern "C" void kernel_launch(void* const* d_in, const int* in_sizes, int n_in,
                              void* d_out, int out_size) {
    const float* x    = (const float*)d_in[0];   // [B,K,D]
    const float* W    = (const float*)d_in[1];   // [D,D]
    const float* bias = (const float*)d_in[2];   // [D]
    float* out = (float*)d_out;                  // [B,K,D]

    cudaFuncSetAttribute(gemm_sigmoid_kernel,
                         cudaFuncAttributeMaxDynamicSharedMemorySize, GEMM_SMEM);

    dim3 ggrid(DD / BN, M_TOTAL / Bb);           // (16, 128)
    gemm_sigmoid_kernel<<<ggrid, GEMM_THREADS, GEMM_SMEM>>>(x, W, bias);

    scan_kernel<<<(BB * DD) / 32, 1024>>>(x, out);
}